// round 1
// baseline (speedup 1.0000x reference)
#include <cuda_runtime.h>

#define D 64
#define L 64
#define BB 8
#define MAT (D*D)        // 4096 elems per matrix
#define NMAT (BB*L)      // 512 matrices

// Scratch (static device globals — no runtime allocation).
// All matrices stored in reciprocal-exp domain: W = exp(-m).
__device__ float g_buf[2][NMAT * MAT];   // ping-pong buffers, 8MB each
__device__ float g_wtab[4 * MAT];        // exp(-p[a+1]) for a in 0..3
__device__ float g_ttab[16 * MAT];       // step-1 pair products W(a) (x) W(b)
__device__ float g_p0tab[MAT];           // exp(-p[0])

__device__ __forceinline__ float frcp(float x) {
    float r;
    asm("rcp.approx.f32 %0, %1;" : "=f"(r) : "f"(x));
    return r;
}

// Core log-semiring matmul in W-domain:
//   out[i,j] = rcp( sum_k rcp( s1[i,k] + s2[k,j] ) )
// s1, s2 in shared memory; 256 threads, each owns a 4x4 output tile.
__device__ __forceinline__ void logmm_core(const float* __restrict__ s1,
                                           const float* __restrict__ s2,
                                           float* __restrict__ out, int t) {
    const int ti = (t >> 4) << 2;   // row tile base
    const int tj = (t & 15) << 2;   // col tile base
    float acc[4][4];
#pragma unroll
    for (int r = 0; r < 4; r++)
#pragma unroll
        for (int c = 0; c < 4; c++) acc[r][c] = 0.f;

#pragma unroll 2
    for (int k = 0; k < D; k += 4) {
        float a[4][4], b[4][4];
#pragma unroll
        for (int r = 0; r < 4; r++)
            *(float4*)&a[r][0] = *(const float4*)&s1[(ti + r) * D + k];
#pragma unroll
        for (int kk = 0; kk < 4; kk++)
            *(float4*)&b[kk][0] = *(const float4*)&s2[(k + kk) * D + tj];
#pragma unroll
        for (int r = 0; r < 4; r++)
#pragma unroll
            for (int kk = 0; kk < 4; kk++)
#pragma unroll
                for (int c = 0; c < 4; c++)
                    acc[r][c] += frcp(a[r][kk] + b[kk][c]);
    }

#pragma unroll
    for (int r = 0; r < 4; r++) {
        float4 v = make_float4(frcp(acc[r][0]), frcp(acc[r][1]),
                               frcp(acc[r][2]), frcp(acc[r][3]));
        *(float4*)&out[(ti + r) * D + tj] = v;
    }
}

// Exp tables: block 0 -> p0tab = exp(-p[0]); blocks 1..4 -> wtab[a-1] = exp(-p[a]).
__global__ void exp_tab_kernel(const float* __restrict__ p) {
    int a = blockIdx.x;
    const float4* src = (const float4*)(p + (size_t)a * MAT);
    float4* dst = (a == 0) ? (float4*)g_p0tab : (float4*)(g_wtab + (size_t)(a - 1) * MAT);
    for (int i = threadIdx.x; i < MAT / 4; i += 256) {
        float4 v = src[i];
        dst[i] = make_float4(expf(-v.x), expf(-v.y), expf(-v.z), expf(-v.w));
    }
}

// Step-1 dedup: only 16 distinct adjacent products exist. ttab[a*4+b] = W(a) (x) W(b).
__global__ void pair_kernel() {
    int a = blockIdx.x >> 2, b = blockIdx.x & 3;
    __shared__ float s1[MAT], s2[MAT];
    for (int i = threadIdx.x; i < MAT / 4; i += 256) {
        ((float4*)s1)[i] = ((const float4*)(g_wtab + (size_t)a * MAT))[i];
        ((float4*)s2)[i] = ((const float4*)(g_wtab + (size_t)b * MAT))[i];
    }
    __syncthreads();
    logmm_core(s1, s2, g_ttab + (size_t)blockIdx.x * MAT, threadIdx.x);
}

// Gather: materialize state-after-step-1 into g_buf[0].
// l==0: W(act[b,0]); l>=1: ttab[act[b,l-1]*4 + act[b,l]].
__global__ void gather_kernel(const int* __restrict__ act) {
    int bl = blockIdx.x;
    int l = bl & (L - 1);
    const float* src = (l == 0)
        ? g_wtab + (size_t)act[bl] * MAT
        : g_ttab + (size_t)(act[bl - 1] * 4 + act[bl]) * MAT;
    float* dst = g_buf[0] + (size_t)bl * MAT;
    for (int i = threadIdx.x; i < MAT / 4; i += 256)
        ((float4*)dst)[i] = ((const float4*)src)[i];
}

// One Hillis-Steele doubling pass: new[l] = old[l-step] (x) old[l] for l>=step, else copy.
__global__ void step_kernel(int step, int sel) {
    const float* src = g_buf[sel];
    float* dst = g_buf[sel ^ 1];
    int bl = blockIdx.x;
    int l = bl & (L - 1);
    int t = threadIdx.x;
    const float* m2 = src + (size_t)bl * MAT;
    float* o = dst + (size_t)bl * MAT;
    if (l < step) {
        for (int i = t; i < MAT / 4; i += 256)
            ((float4*)o)[i] = ((const float4*)m2)[i];
        return;
    }
    __shared__ float s1[MAT], s2[MAT];
    const float* m1 = src + (size_t)(bl - step) * MAT;
    for (int i = t; i < MAT / 4; i += 256) {
        ((float4*)s1)[i] = ((const float4*)m1)[i];
        ((float4*)s2)[i] = ((const float4*)m2)[i];
    }
    __syncthreads();
    logmm_core(s1, s2, o, t);
}

// Final: x = init_row (x) PM, then y = x (x) p0, output in log domain.
//   Xw[j]  = rcp( sum_k rcp( exp(-init[k]) + W[k,j] ) )
//   y[j]   = log( sum_k rcp( Xw[k] + P0w[k,j] ) )
__global__ void final_kernel(const float* __restrict__ init_vec,
                             float* __restrict__ out) {
    int bl = blockIdx.x;
    const float* W = g_buf[1] + (size_t)bl * MAT;  // after 6 passes, result in buf 1
    __shared__ float sw[MAT];
    __shared__ float ci[D];
    __shared__ float xw[D];
    int t = threadIdx.x;  // 64 threads
    for (int i = t; i < MAT / 4; i += 64)
        ((float4*)sw)[i] = ((const float4*)W)[i];
    ci[t] = expf(-init_vec[t]);
    __syncthreads();

    float s = 0.f;
#pragma unroll 8
    for (int k = 0; k < D; k++)
        s += frcp(ci[k] + sw[k * D + t]);
    xw[t] = frcp(s);
    __syncthreads();

    float s2 = 0.f;
#pragma unroll 8
    for (int k = 0; k < D; k++)
        s2 += frcp(xw[k] + g_p0tab[k * D + t]);
    out[(size_t)bl * D + t] = logf(s2);
}

extern "C" void kernel_launch(void* const* d_in, const int* in_sizes, int n_in,
                              void* d_out, int out_size) {
    const float* p        = (const float*)d_in[0];  // (5, 64, 64)
    const float* init_vec = (const float*)d_in[1];  // (64,)
    const int*   act      = (const int*)d_in[2];    // (8, 64)
    float* out = (float*)d_out;                     // (8, 64, 64)

    exp_tab_kernel<<<5, 256>>>(p);
    pair_kernel<<<16, 256>>>();
    gather_kernel<<<512, 256>>>(act);       // result of step=1 pass -> buf0
    step_kernel<<<512, 256>>>(2, 0);        // buf0 -> buf1
    step_kernel<<<512, 256>>>(4, 1);        // buf1 -> buf0
    step_kernel<<<512, 256>>>(8, 0);        // buf0 -> buf1
    step_kernel<<<512, 256>>>(16, 1);       // buf1 -> buf0
    step_kernel<<<512, 256>>>(32, 0);       // buf0 -> buf1
    final_kernel<<<512, 64>>>(init_vec, out);
}

// round 2
// speedup vs baseline: 1.4460x; 1.4460x over previous
#include <cuda_runtime.h>

#define D 64
#define L 64
#define BB 8
#define MAT (D*D)          // 4096 floats per matrix
#define NMAT (BB*L)        // 512 matrices
#define PA 68              // padded smem pitch for A (kills 8-way bank conflict)

// All matrices in reciprocal-exp domain: W = exp(-m).
// log-semiring matmul:  out[i,j] = rcp( sum_k rcp( A[i,k] + B[k,j] ) )
__device__ float g_buf0[NMAT * MAT];   // 8MB
__device__ float g_buf1[NMAT * MAT];   // 8MB
__device__ float g_wtab[4 * MAT];      // exp(-p[a+1])
__device__ float g_ttab[16 * MAT];     // pair products  W(a) (x) W(b)
__device__ float g_qtab[256 * MAT];    // quad products  pair (x) pair   (4MB)
__device__ float g_p0tab[MAT];         // exp(-p[0])

__device__ __forceinline__ float frcp(float x) {
    float r;
    asm("rcp.approx.f32 %0, %1;" : "=f"(r) : "f"(x));
    return r;
}

// ---------------------------------------------------------------------------
// Quarter matmul: one CTA computes a 64x16 column slice (quarter q) of
// Dst = A (x) B.   256 threads, thread = (row, colgroup of 4).
// ---------------------------------------------------------------------------
__device__ __forceinline__ void mm_quarter(const float* __restrict__ A,
                                           const float* __restrict__ B,
                                           float* __restrict__ Dst, int q) {
    __shared__ float sA[D * PA];       // full A, padded pitch
    __shared__ float sB[D * 16];       // quarter of B
    const int t = threadIdx.x;

    // stage A (4 float4 per thread)
#pragma unroll
    for (int i = 0; i < 4; i++) {
        int idx = t + i * 256;          // float4 index 0..1023
        int r = idx >> 4, c = idx & 15;
        float4 v = ((const float4*)A)[idx];
        *(float4*)&sA[r * PA + c * 4] = v;
    }
    // stage B quarter (1 float4 per thread)
    {
        int k = t >> 2, g = t & 3;
        float4 v = *(const float4*)&B[k * D + q * 16 + g * 4];
        *(float4*)&sB[k * 16 + g * 4] = v;
    }
    __syncthreads();

    const int row = t >> 2, cg = t & 3;
    const float* ap = &sA[row * PA];
    const float* bp = &sB[cg * 4];
    float a0 = 0.f, a1 = 0.f, a2 = 0.f, a3 = 0.f;
#pragma unroll
    for (int k4 = 0; k4 < 16; k4++) {
        float4 av = *(const float4*)&ap[k4 * 4];
        float4 bA = *(const float4*)&bp[(k4 * 4 + 0) * 16];
        float4 bB = *(const float4*)&bp[(k4 * 4 + 1) * 16];
        float4 bC = *(const float4*)&bp[(k4 * 4 + 2) * 16];
        float4 bD = *(const float4*)&bp[(k4 * 4 + 3) * 16];
        a0 += frcp(av.x + bA.x); a1 += frcp(av.x + bA.y);
        a2 += frcp(av.x + bA.z); a3 += frcp(av.x + bA.w);
        a0 += frcp(av.y + bB.x); a1 += frcp(av.y + bB.y);
        a2 += frcp(av.y + bB.z); a3 += frcp(av.y + bB.w);
        a0 += frcp(av.z + bC.x); a1 += frcp(av.z + bC.y);
        a2 += frcp(av.z + bC.z); a3 += frcp(av.z + bC.w);
        a0 += frcp(av.w + bD.x); a1 += frcp(av.w + bD.y);
        a2 += frcp(av.w + bD.z); a3 += frcp(av.w + bD.w);
    }
    float4 o = make_float4(frcp(a0), frcp(a1), frcp(a2), frcp(a3));
    *(float4*)&Dst[row * D + q * 16 + cg * 4] = o;
}

// ---------------------------------------------------------------------------
// "Latest value" resolver: where does value of index m live before pass 2^slog?
//   m<2            -> buf0 (step-1 singles / pair copy)
//   pass level p = min(floor(log2 m), slog-1)
//   p==1 (pass-2): m==2 -> tri in buf1, else quad table via act index
//   else           -> buf parity (pass4->buf0, pass8->buf1, pass16->buf0, pass32->buf1)
// ---------------------------------------------------------------------------
__device__ __forceinline__ const float* latest(const int* __restrict__ act,
                                               int b, int m, int slog) {
    size_t off = (size_t)(b * L + m) * MAT;
    if (m < 2) return g_buf0 + off;
    int p = 31 - __clz(m);
    if (p > slog - 1) p = slog - 1;
    if (p == 1) {
        if (m == 2) return g_buf1 + off;
        const int* a = act + b * L + (m - 3);
        int idx = ((a[0] * 4 + a[1]) * 4 + a[2]) * 4 + a[3];
        return g_qtab + (size_t)idx * MAT;
    }
    return (p & 1) ? g_buf1 + off : g_buf0 + off;
}

// ---------------------------------------------------------------------------
// Kernels
// ---------------------------------------------------------------------------
__global__ void exp_tab_kernel(const float* __restrict__ p) {
    int a = blockIdx.x;
    const float4* src = (const float4*)(p + (size_t)a * MAT);
    float4* dst = (a == 0) ? (float4*)g_p0tab
                           : (float4*)(g_wtab + (size_t)(a - 1) * MAT);
    for (int i = threadIdx.x; i < MAT / 4; i += 256) {
        float4 v = src[i];
        dst[i] = make_float4(expf(-v.x), expf(-v.y), expf(-v.z), expf(-v.w));
    }
}

// 16 pair products, 4 quarters each = 64 CTAs
__global__ void __launch_bounds__(256, 5) pair_kernel() {
    int pidx = blockIdx.x >> 2, q = blockIdx.x & 3;
    int a = pidx >> 2, b = pidx & 3;
    mm_quarter(g_wtab + (size_t)a * MAT, g_wtab + (size_t)b * MAT,
               g_ttab + (size_t)pidx * MAT, q);
}

// quads (1024) + tris (32) + step-1 copies for l=0,1 (16) = 1072 CTAs
__global__ void __launch_bounds__(256, 5) stage2_kernel(const int* __restrict__ act) {
    int bid = blockIdx.x;
    if (bid < 1024) {
        int qidx = bid >> 2, q = bid & 3;
        mm_quarter(g_ttab + (size_t)(qidx >> 4) * MAT,
                   g_ttab + (size_t)(qidx & 15) * MAT,
                   g_qtab + (size_t)qidx * MAT, q);
    } else if (bid < 1056) {
        int i = bid - 1024;
        int b = i >> 2, q = i & 3;
        int a0 = act[b * L], a12 = act[b * L + 1] * 4 + act[b * L + 2];
        mm_quarter(g_wtab + (size_t)a0 * MAT, g_ttab + (size_t)a12 * MAT,
                   g_buf1 + (size_t)(b * L + 2) * MAT, q);
    } else {
        int i = bid - 1056;                 // 0..15
        int b = i >> 1, which = i & 1;      // l = 0 or 1
        const float* src = which
            ? g_ttab + (size_t)(act[b * L] * 4 + act[b * L + 1]) * MAT
            : g_wtab + (size_t)act[b * L] * MAT;
        float* dst = g_buf0 + (size_t)(b * L + which) * MAT;
        for (int j = threadIdx.x; j < MAT / 4; j += 256)
            ((float4*)dst)[j] = ((const float4*)src)[j];
    }
}

// Doubling pass for step = 2^slog (slog >= 2). No copies; writes only l >= step.
__global__ void __launch_bounds__(256, 5) step_kernel(const int* __restrict__ act,
                                                      int slog) {
    int step = 1 << slog;
    int n = L - step;
    int idx = blockIdx.x >> 2, q = blockIdx.x & 3;
    int b = idx / n;
    int l = step + (idx - b * n);
    const float* A = latest(act, b, l - step, slog);
    const float* Bm = latest(act, b, l, slog);
    float* dstbuf = (slog & 1) ? g_buf1 : g_buf0;
    mm_quarter(A, Bm, dstbuf + (size_t)(b * L + l) * MAT, q);
}

// Final: x = init (x) PM ; y = x (x) p0 ; output in log domain.
__global__ void final_kernel(const int* __restrict__ act,
                             const float* __restrict__ init_vec,
                             float* __restrict__ out) {
    int bl = blockIdx.x;
    int b = bl >> 6, l = bl & 63;
    const float* W = latest(act, b, l, 6);
    __shared__ float ci[D];
    __shared__ float xw[D];
    int t = threadIdx.x;                   // 64 threads
    ci[t] = expf(-init_vec[t]);
    __syncthreads();

    float s = 0.f;
#pragma unroll 8
    for (int k = 0; k < D; k++)
        s += frcp(ci[k] + W[k * D + t]);
    xw[t] = frcp(s);
    __syncthreads();

    float s2 = 0.f;
#pragma unroll 8
    for (int k = 0; k < D; k++)
        s2 += frcp(xw[k] + g_p0tab[k * D + t]);
    out[(size_t)bl * D + t] = logf(s2);
}

extern "C" void kernel_launch(void* const* d_in, const int* in_sizes, int n_in,
                              void* d_out, int out_size) {
    const float* p        = (const float*)d_in[0];  // (5, 64, 64)
    const float* init_vec = (const float*)d_in[1];  // (64,)
    const int*   act      = (const int*)d_in[2];    // (8, 64)
    float* out = (float*)d_out;                     // (8, 64, 64)

    exp_tab_kernel<<<5, 256>>>(p);
    pair_kernel<<<64, 256>>>();
    stage2_kernel<<<1072, 256>>>(act);
    step_kernel<<<8 * (L - 4)  * 4, 256>>>(act, 2);   // 1920 CTAs -> buf0
    step_kernel<<<8 * (L - 8)  * 4, 256>>>(act, 3);   // 1792 CTAs -> buf1
    step_kernel<<<8 * (L - 16) * 4, 256>>>(act, 4);   // 1536 CTAs -> buf0
    step_kernel<<<8 * (L - 32) * 4, 256>>>(act, 5);   // 1024 CTAs -> buf1
    final_kernel<<<512, 64>>>(act, init_vec, out);
}